// round 1
// baseline (speedup 1.0000x reference)
#include <cuda_runtime.h>
#include <cuda_bf16.h>
#include <math.h>

// ---------------- scratch (device globals: allocation-free) ----------------
__device__ float g_buf1[64 * 64 * 64 * 64];   // 64ch @ 64x64 (conv1 out, tc1 out)
__device__ float g_buf2[64 * 128 * 32 * 32];  // 128ch @ 32x32
__device__ float g_buf3[64 * 128 * 32 * 32];  // 128ch @ 32x32
__device__ float g_buf4[64 * 64 * 32 * 32];   // 64ch @ 32x32 (res mid / Zq)
__device__ float g_buf5[64 * 64 * 32 * 32];   // Ze
__device__ float g_counts[512];
__device__ float g_loss[1];

// ---------------- tiled direct conv: K x K, stride S, pad 1 ----------------
// block = 256 threads; covers one (n, 4-co group, 32x32 output tile).
// each thread: 4 horizontally-adjacent pixels x 4 co.
template <int K, int S, int CIN>
__global__ void __launch_bounds__(256) conv_tiled(
    const float* __restrict__ in, const float* __restrict__ w,
    const float* __restrict__ bias, const float* __restrict__ resid,
    float* __restrict__ out, int Cout, int Hin, int Win, int Hout, int Wout,
    int in_relu, int out_relu)
{
    constexpr int P = 1;
    constexpr int TI = 31 * S + K;          // input tile side
    constexpr int TILE_N = TI * TI;
    constexpr int NS = (TILE_N + 255) / 256;
    constexpr int RW = 3 * S + K;           // per-thread input row width

    __shared__ float tile[TILE_N];
    __shared__ float4 wsm[CIN * K * K];

    const int tid = threadIdx.x;
    const int co0 = blockIdx.x * 4;
    const int n = blockIdx.y;
    const int tilesX = Wout >> 5;
    const int ty = blockIdx.z / tilesX, tx = blockIdx.z % tilesX;
    const int r0 = ty * 32, c0 = tx * 32;

    // preload weights for 4 output channels, interleaved as float4 over co
    float* wsm_f = (float*)wsm;
#pragma unroll
    for (int c = 0; c < 4; c++) {
        const float* wp = w + (size_t)(co0 + c) * CIN * K * K;
        for (int j = tid; j < CIN * K * K; j += 256)
            wsm_f[j * 4 + c] = wp[j];
    }

    // precompute tile-load global offsets (or -1 for zero padding)
    int goff[NS];
#pragma unroll
    for (int s = 0; s < NS; s++) {
        int i = tid + s * 256;
        goff[s] = -1;
        if (i < TILE_N) {
            int tr = i / TI, tc = i % TI;
            int gr = r0 * S - P + tr, gc = c0 * S - P + tc;
            if (gr >= 0 && gr < Hin && gc >= 0 && gc < Win) goff[s] = gr * Win + gc;
        }
    }

    const int row = tid >> 3;
    const int col4 = (tid & 7) << 2;

    float acc[4][4];
#pragma unroll
    for (int a = 0; a < 4; a++)
#pragma unroll
        for (int b = 0; b < 4; b++) acc[a][b] = 0.f;

    const float* inb = in + (size_t)n * CIN * Hin * Win;

    for (int ci = 0; ci < CIN; ci++) {
        __syncthreads();
        const float* ip = inb + (size_t)ci * Hin * Win;
#pragma unroll
        for (int s = 0; s < NS; s++) {
            int i = tid + s * 256;
            if (i < TILE_N) {
                float v = (goff[s] >= 0) ? ip[goff[s]] : 0.f;
                if (in_relu) v = fmaxf(v, 0.f);
                tile[i] = v;
            }
        }
        __syncthreads();

        float rg[K][RW];
#pragma unroll
        for (int a = 0; a < K; a++)
#pragma unroll
            for (int b = 0; b < RW; b++)
                rg[a][b] = tile[(row * S + a) * TI + col4 * S + b];

        const float4* wp = wsm + ci * K * K;
#pragma unroll
        for (int kh = 0; kh < K; kh++)
#pragma unroll
            for (int kw = 0; kw < K; kw++) {
                float4 wv = wp[kh * K + kw];
#pragma unroll
                for (int px = 0; px < 4; px++) {
                    float iv = rg[kh][px * S + kw];
                    acc[px][0] = fmaf(iv, wv.x, acc[px][0]);
                    acc[px][1] = fmaf(iv, wv.y, acc[px][1]);
                    acc[px][2] = fmaf(iv, wv.z, acc[px][2]);
                    acc[px][3] = fmaf(iv, wv.w, acc[px][3]);
                }
            }
    }

#pragma unroll
    for (int c = 0; c < 4; c++) {
        int co = co0 + c;
        float bv = bias ? bias[co] : 0.f;
        size_t base = (((size_t)n * Cout + co) * Hout + r0 + row) * Wout + c0 + col4;
#pragma unroll
        for (int px = 0; px < 4; px++) {
            float v = acc[px][c] + bv;
            if (resid) v += resid[base + px];
            if (out_relu) v = fmaxf(v, 0.f);
            out[base + px] = v;
        }
    }
}

// ---------------- 1x1 conv over 32x32 planes (HW = 1024) ----------------
// block = 256 threads; one (n, 4-co group); each thread 4 consecutive pixels.
__global__ void __launch_bounds__(256) conv1x1(
    const float* __restrict__ in, const float* __restrict__ w,
    const float* __restrict__ bias, const float* __restrict__ resid,
    float* __restrict__ out, int Cin, int Cout, int in_relu, int out_relu)
{
    __shared__ float4 wsm[128];
    const int tid = threadIdx.x;
    const int co0 = blockIdx.x * 4;
    const int n = blockIdx.y;
    float* wsm_f = (float*)wsm;
#pragma unroll
    for (int c = 0; c < 4; c++)
        for (int j = tid; j < Cin; j += 256)
            wsm_f[j * 4 + c] = w[(size_t)(co0 + c) * Cin + j];
    __syncthreads();

    const int px0 = tid * 4;
    const float* ip = in + (size_t)n * Cin * 1024 + px0;

    float4 acc[4];
#pragma unroll
    for (int c = 0; c < 4; c++) acc[c] = make_float4(0.f, 0.f, 0.f, 0.f);

    for (int ci = 0; ci < Cin; ci++) {
        float4 v = *(const float4*)(ip + (size_t)ci * 1024);
        if (in_relu) {
            v.x = fmaxf(v.x, 0.f); v.y = fmaxf(v.y, 0.f);
            v.z = fmaxf(v.z, 0.f); v.w = fmaxf(v.w, 0.f);
        }
        float4 wv = wsm[ci];
        acc[0].x = fmaf(v.x, wv.x, acc[0].x); acc[0].y = fmaf(v.y, wv.x, acc[0].y);
        acc[0].z = fmaf(v.z, wv.x, acc[0].z); acc[0].w = fmaf(v.w, wv.x, acc[0].w);
        acc[1].x = fmaf(v.x, wv.y, acc[1].x); acc[1].y = fmaf(v.y, wv.y, acc[1].y);
        acc[1].z = fmaf(v.z, wv.y, acc[1].z); acc[1].w = fmaf(v.w, wv.y, acc[1].w);
        acc[2].x = fmaf(v.x, wv.z, acc[2].x); acc[2].y = fmaf(v.y, wv.z, acc[2].y);
        acc[2].z = fmaf(v.z, wv.z, acc[2].z); acc[2].w = fmaf(v.w, wv.z, acc[2].w);
        acc[3].x = fmaf(v.x, wv.w, acc[3].x); acc[3].y = fmaf(v.y, wv.w, acc[3].y);
        acc[3].z = fmaf(v.z, wv.w, acc[3].z); acc[3].w = fmaf(v.w, wv.w, acc[3].w);
    }

#pragma unroll
    for (int c = 0; c < 4; c++) {
        int co = co0 + c;
        float bv = bias ? bias[co] : 0.f;
        size_t base = ((size_t)n * Cout + co) * 1024 + px0;
        float4 r = acc[c];
        r.x += bv; r.y += bv; r.z += bv; r.w += bv;
        if (resid) {
            float4 rs = *(const float4*)(resid + base);
            r.x += rs.x; r.y += rs.y; r.z += rs.z; r.w += rs.w;
        }
        if (out_relu) {
            r.x = fmaxf(r.x, 0.f); r.y = fmaxf(r.y, 0.f);
            r.z = fmaxf(r.z, 0.f); r.w = fmaxf(r.w, 0.f);
        }
        *(float4*)(out + base) = r;
    }
}

// ---------------- ConvTranspose2d k=4, s=2, p=1 (gather form) ----------------
// oh = 2*ih - 1 + kh  => ih = (oh+1-kh)/2 ; exactly 2 valid kh (and kw) per output.
template <int CIN>
__global__ void __launch_bounds__(256) convt421(
    const float* __restrict__ in, const float* __restrict__ w,
    const float* __restrict__ bias, float* __restrict__ out,
    int Cout, int Hin, int Win, int Hout, int Wout, int in_relu, int out_relu)
{
    __shared__ float tile[18 * 18];
    __shared__ float4 wsm[CIN * 16];

    const int tid = threadIdx.x;
    const int co0 = blockIdx.x * 4;
    const int n = blockIdx.y;
    const int tilesX = Wout >> 5;
    const int ty = blockIdx.z / tilesX, tx = blockIdx.z % tilesX;
    const int r0 = ty * 32, c0 = tx * 32;
    const int base_i = (r0 >> 1) - 1, base_j = (c0 >> 1) - 1;

    float* wsm_f = (float*)wsm;
#pragma unroll
    for (int c = 0; c < 4; c++) {
        int co = co0 + c;
        for (int j = tid; j < CIN * 16; j += 256)
            wsm_f[j * 4 + c] =
                (co < Cout) ? w[((size_t)(j >> 4) * Cout + co) * 16 + (j & 15)] : 0.f;
    }

    const int row = tid >> 3;
    const int col4 = (tid & 7) << 2;
    const int oh = r0 + row;
    const int kh_a = (oh + 1) & 1;
    const int ih_a = (oh + 1 - kh_a) >> 1;
    const int ta = ih_a - base_i;
    const int tb = ta - 1;

    float acc[4][4];
#pragma unroll
    for (int a = 0; a < 4; a++)
#pragma unroll
        for (int b = 0; b < 4; b++) acc[a][b] = 0.f;

    const float* inb = in + (size_t)n * CIN * Hin * Win;

    for (int ci = 0; ci < CIN; ci++) {
        __syncthreads();
        for (int i = tid; i < 324; i += 256) {
            int tr = i / 18, tc = i % 18;
            int gi = base_i + tr, gj = base_j + tc;
            float v = 0.f;
            if (gi >= 0 && gi < Hin && gj >= 0 && gj < Win)
                v = inb[((size_t)ci * Hin + gi) * Win + gj];
            if (in_relu) v = fmaxf(v, 0.f);
            tile[i] = v;
        }
        __syncthreads();

        const float4* wp = wsm + ci * 16;
#pragma unroll
        for (int px = 0; px < 4; px++) {
            int ow = c0 + col4 + px;
            int kw_a = (ow + 1) & 1;
            int ja = ((ow + 1 - kw_a) >> 1) - base_j;
            int jb = ja - 1;
            float iaa = tile[ta * 18 + ja], iab = tile[ta * 18 + jb];
            float iba = tile[tb * 18 + ja], ibb = tile[tb * 18 + jb];
            float4 waa = wp[kh_a * 4 + kw_a];
            float4 wab = wp[kh_a * 4 + kw_a + 2];
            float4 wba = wp[(kh_a + 2) * 4 + kw_a];
            float4 wbb = wp[(kh_a + 2) * 4 + kw_a + 2];
            acc[px][0] = fmaf(iaa, waa.x, fmaf(iab, wab.x, fmaf(iba, wba.x, fmaf(ibb, wbb.x, acc[px][0]))));
            acc[px][1] = fmaf(iaa, waa.y, fmaf(iab, wab.y, fmaf(iba, wba.y, fmaf(ibb, wbb.y, acc[px][1]))));
            acc[px][2] = fmaf(iaa, waa.z, fmaf(iab, wab.z, fmaf(iba, wba.z, fmaf(ibb, wbb.z, acc[px][2]))));
            acc[px][3] = fmaf(iaa, waa.w, fmaf(iab, wab.w, fmaf(iba, wba.w, fmaf(ibb, wbb.w, acc[px][3]))));
        }
    }

#pragma unroll
    for (int c = 0; c < 4; c++) {
        int co = co0 + c;
        if (co >= Cout) continue;
        float bv = bias ? bias[co] : 0.f;
        size_t base = (((size_t)n * Cout + co) * Hout + oh) * Wout + c0 + col4;
#pragma unroll
        for (int px = 0; px < 4; px++) {
            float v = acc[px][c] + bv;
            if (out_relu) v = fmaxf(v, 0.f);
            out[base + px] = v;
        }
    }
}

// ---------------- VQ: distances, argmin, Zq gather, loss, histogram ----------------
__global__ void __launch_bounds__(512) vq_kernel(
    const float* __restrict__ Ze, const float* __restrict__ E,
    float* __restrict__ Zq, float* __restrict__ counts, float* __restrict__ loss_sum)
{
    extern __shared__ float Es[];          // 512*64 floats = 128 KB
    __shared__ float e2s[512];
    __shared__ float red[512];
    const int tid = threadIdx.x;

    for (int i = tid * 4; i < 512 * 64; i += 512 * 4)
        *(float4*)&Es[i] = *(const float4*)&E[i];
    __syncthreads();

    {
        const float* er = &Es[tid * 64];
        float s = 0.f;
#pragma unroll
        for (int d = 0; d < 64; d++) s = fmaf(er[d], er[d], s);
        e2s[tid] = s;
    }
    __syncthreads();

    const int vi = blockIdx.x * 512 + tid;
    const int b = vi >> 10;
    const int hw = vi & 1023;
    const float* zp = Ze + (size_t)b * 64 * 1024 + hw;

    float v[64];
#pragma unroll
    for (int d = 0; d < 64; d++) v[d] = zp[(size_t)d * 1024];
    float sv = 0.f;
#pragma unroll
    for (int d = 0; d < 64; d++) sv = fmaf(v[d], v[d], sv);

    float best = 3.402823466e38f;
    int bi = 0;
    for (int k = 0; k < 512; k++) {
        const float4* er = (const float4*)&Es[k * 64];
        float dot = 0.f;
#pragma unroll
        for (int j = 0; j < 16; j++) {
            float4 e = er[j];
            dot = fmaf(v[4 * j + 0], e.x, dot);
            dot = fmaf(v[4 * j + 1], e.y, dot);
            dot = fmaf(v[4 * j + 2], e.z, dot);
            dot = fmaf(v[4 * j + 3], e.w, dot);
        }
        float dist = sv + e2s[k] - 2.f * dot;
        if (dist < best) { best = dist; bi = k; }
    }

    float le = 0.f;
    float* qp = Zq + (size_t)b * 64 * 1024 + hw;
    const float* eb = &Es[bi * 64];
#pragma unroll
    for (int d = 0; d < 64; d++) {
        float q = eb[d];
        qp[(size_t)d * 1024] = q;
        float dd = q - v[d];
        le = fmaf(dd, dd, le);
    }
    atomicAdd(&counts[bi], 1.0f);

    red[tid] = le;
    __syncthreads();
    for (int s = 256; s > 0; s >>= 1) {
        if (tid < s) red[tid] += red[tid + s];
        __syncthreads();
    }
    if (tid == 0) atomicAdd(loss_sum, red[0]);
}

__global__ void zero_small(float* counts, float* loss) {
    int t = blockIdx.x * blockDim.x + threadIdx.x;
    if (t < 512) counts[t] = 0.f;
    if (t == 0) loss[0] = 0.f;
}

__global__ void finalize_kernel(const float* __restrict__ counts,
                                const float* __restrict__ loss_sum,
                                float* __restrict__ out, int out_size) {
    __shared__ float red[512];
    int tid = threadIdx.x;
    float c = counts[tid];
    float p = c * (1.0f / 65536.0f);
    red[tid] = p * log2f(p + 1e-10f);
    __syncthreads();
    for (int s = 256; s > 0; s >>= 1) {
        if (tid < s) red[tid] += red[tid + s];
        __syncthreads();
    }
    if (tid == 0) {
        float ent = -red[0];
        float mse = loss_sum[0] * (1.0f / 4194304.0f);  // mean over 65536*64
        out[0] = mse + 0.25f * mse;                      // q + BETA*e
        out[out_size - 3] = mse;                         // e_latent_loss
        out[out_size - 2] = mse;                         // q_latent_loss
        out[out_size - 1] = exp2f(ent);                  // est_words
    }
}

// ---------------- host launcher ----------------
extern "C" void kernel_launch(void* const* d_in, const int* in_sizes, int n_in,
                              void* d_out, int out_size) {
    const float* x         = (const float*)d_in[0];
    const float* enc_w1    = (const float*)d_in[1];
    const float* enc_b1    = (const float*)d_in[2];
    const float* enc_w2    = (const float*)d_in[3];
    const float* enc_b2    = (const float*)d_in[4];
    const float* enc_w3    = (const float*)d_in[5];
    const float* enc_b3    = (const float*)d_in[6];
    const float* enc_w4    = (const float*)d_in[7];
    const float* enc_b4    = (const float*)d_in[8];
    const float* enc_res_w1= (const float*)d_in[9];
    const float* enc_res_w2= (const float*)d_in[10];
    const float* enc_adj_w = (const float*)d_in[11];
    const float* enc_adj_b = (const float*)d_in[12];
    const float* E         = (const float*)d_in[13];
    const float* dec_adj_w = (const float*)d_in[14];
    const float* dec_adj_b = (const float*)d_in[15];
    const float* dec_res_w1= (const float*)d_in[16];
    const float* dec_res_w2= (const float*)d_in[17];
    const float* tc1_w     = (const float*)d_in[18];
    const float* tc1_b     = (const float*)d_in[19];
    const float* tc2_w     = (const float*)d_in[20];
    const float* tc2_b     = (const float*)d_in[21];
    float* out = (float*)d_out;

    float *b1, *b2, *b3, *b4, *b5, *cnt, *lsum;
    cudaGetSymbolAddress((void**)&b1, g_buf1);
    cudaGetSymbolAddress((void**)&b2, g_buf2);
    cudaGetSymbolAddress((void**)&b3, g_buf3);
    cudaGetSymbolAddress((void**)&b4, g_buf4);
    cudaGetSymbolAddress((void**)&b5, g_buf5);
    cudaGetSymbolAddress((void**)&cnt, g_counts);
    cudaGetSymbolAddress((void**)&lsum, g_loss);

    cudaFuncSetAttribute(vq_kernel, cudaFuncAttributeMaxDynamicSharedMemorySize, 131072);

    const int B = 64;

    // -------- encoder --------
    conv_tiled<4, 2, 3><<<dim3(16, B, 4), 256>>>(x, enc_w1, enc_b1, nullptr, b1,
                                                 64, 128, 128, 64, 64, 0, 1);
    conv_tiled<4, 2, 64><<<dim3(32, B, 1), 256>>>(b1, enc_w2, enc_b2, nullptr, b2,
                                                  128, 64, 64, 32, 32, 0, 1);
    conv_tiled<3, 1, 128><<<dim3(32, B, 1), 256>>>(b2, enc_w3, enc_b3, nullptr, b3,
                                                   128, 32, 32, 32, 32, 0, 1);
    conv_tiled<3, 1, 128><<<dim3(32, B, 1), 256>>>(b3, enc_w4, enc_b4, nullptr, b2,
                                                   128, 32, 32, 32, 32, 0, 0);
    // res block 1
    conv_tiled<3, 1, 128><<<dim3(16, B, 1), 256>>>(b2, enc_res_w1, nullptr, nullptr, b4,
                                                   64, 32, 32, 32, 32, 1, 0);
    conv1x1<<<dim3(32, B), 256>>>(b4, enc_res_w2, nullptr, b2, b3, 64, 128, 1, 0);
    // res block 2
    conv_tiled<3, 1, 128><<<dim3(16, B, 1), 256>>>(b3, enc_res_w1 + 64 * 128 * 9, nullptr,
                                                   nullptr, b4, 64, 32, 32, 32, 32, 1, 0);
    conv1x1<<<dim3(32, B), 256>>>(b4, enc_res_w2 + 128 * 64, nullptr, b3, b2, 64, 128, 1, 0);
    // enc_adj (input gets the res_stack's final relu via in_relu)
    conv1x1<<<dim3(16, B), 256>>>(b2, enc_adj_w, enc_adj_b, nullptr, b5, 128, 64, 1, 0);

    // -------- vector quantizer --------
    zero_small<<<2, 256>>>(cnt, lsum);
    vq_kernel<<<128, 512, 131072>>>(b5, E, b4, cnt, lsum);

    // -------- decoder --------
    conv_tiled<3, 1, 64><<<dim3(32, B, 1), 256>>>(b4, dec_adj_w, dec_adj_b, nullptr, b2,
                                                  128, 32, 32, 32, 32, 0, 0);
    conv_tiled<3, 1, 128><<<dim3(16, B, 1), 256>>>(b2, dec_res_w1, nullptr, nullptr, b4,
                                                   64, 32, 32, 32, 32, 1, 0);
    conv1x1<<<dim3(32, B), 256>>>(b4, dec_res_w2, nullptr, b2, b3, 64, 128, 1, 0);
    conv_tiled<3, 1, 128><<<dim3(16, B, 1), 256>>>(b3, dec_res_w1 + 64 * 128 * 9, nullptr,
                                                   nullptr, b4, 64, 32, 32, 32, 32, 1, 0);
    conv1x1<<<dim3(32, B), 256>>>(b4, dec_res_w2 + 128 * 64, nullptr, b3, b2, 64, 128, 1, 0);

    convt421<128><<<dim3(16, B, 4), 256>>>(b2, tc1_w, tc1_b, b1,
                                           64, 32, 32, 64, 64, 1, 1);
    convt421<64><<<dim3(1, B, 16), 256>>>(b1, tc2_w, tc2_b, out + 1,
                                          3, 64, 64, 128, 128, 0, 0);

    finalize_kernel<<<1, 512>>>(cnt, lsum, out, out_size);
}